// round 1
// baseline (speedup 1.0000x reference)
#include <cuda_runtime.h>

#define BATCH 4
#define SEQ   1024
#define NXD   1024
#define NHEAD 16
#define HDIM  64

// Scratch (allocation-free rule: __device__ globals)
__device__ float g_q[(size_t)BATCH * NHEAD * SEQ * HDIM];   // 16 MB, [B,NH,S,HD]
__device__ float g_a[(size_t)BATCH * SEQ * NXD];            // 16 MB, [B,S,NX]

// ---------------------------------------------------------------------------
// GEMM 1: qkv = x @ w_attn + b_attn ; scatter into q-scratch and present(k,v)
// A: [4096,1024] row-major, B: [1024,3072] row-major
// ---------------------------------------------------------------------------
__global__ void __launch_bounds__(256) gemm_qkv_kernel(
    const float* __restrict__ A, const float* __restrict__ B,
    const float* __restrict__ bias, float* __restrict__ present)
{
    const int K = 1024, N = 3072;
    __shared__ float As[8][128];
    __shared__ float Bs[8][128];
    const int t = threadIdx.x;
    const int bm = blockIdx.y * 128;
    const int bn = blockIdx.x * 128;
    const int arow = t >> 1, acol = (t & 1) * 4;
    const int brow = t >> 5, bcol = (t & 31) * 4;
    const int ty = t >> 4, tx = t & 15;

    float acc[8][8];
#pragma unroll
    for (int i = 0; i < 8; i++)
#pragma unroll
        for (int j = 0; j < 8; j++) acc[i][j] = 0.f;

    for (int k0 = 0; k0 < K; k0 += 8) {
        float4 av = *(const float4*)(A + (size_t)(bm + arow) * K + k0 + acol);
        As[acol + 0][arow] = av.x;
        As[acol + 1][arow] = av.y;
        As[acol + 2][arow] = av.z;
        As[acol + 3][arow] = av.w;
        *(float4*)(&Bs[brow][bcol]) =
            *(const float4*)(B + (size_t)(k0 + brow) * N + bn + bcol);
        __syncthreads();
#pragma unroll
        for (int kk = 0; kk < 8; kk++) {
            float ar[8], br[8];
            *(float4*)(ar)     = *(const float4*)(&As[kk][ty * 8]);
            *(float4*)(ar + 4) = *(const float4*)(&As[kk][ty * 8 + 4]);
            *(float4*)(br)     = *(const float4*)(&Bs[kk][tx * 8]);
            *(float4*)(br + 4) = *(const float4*)(&Bs[kk][tx * 8 + 4]);
#pragma unroll
            for (int i = 0; i < 8; i++)
#pragma unroll
                for (int j = 0; j < 8; j++) acc[i][j] += ar[i] * br[j];
        }
        __syncthreads();
    }

    // epilogue: scatter to q / k / v in [B,NH,S,HD]
#pragma unroll
    for (int i = 0; i < 8; i++) {
        int m = bm + ty * 8 + i;
        int b = m >> 10, s = m & 1023;
#pragma unroll
        for (int j = 0; j < 8; j++) {
            int n = bn + tx * 8 + j;
            float v = acc[i][j] + bias[n];
            int sec = n >> 10;
            int hn = n & 1023;
            int h = hn >> 6, d = hn & 63;
            size_t idx = (((size_t)b * NHEAD + h) * SEQ + s) * HDIM + d;
            if (sec == 0)      g_q[idx] = v;
            else if (sec == 1) present[idx] = v;
            else               present[(size_t)BATCH * NHEAD * SEQ * HDIM + idx] = v;
        }
    }
}

// ---------------------------------------------------------------------------
// Attention: flash-style, per (b,h,q_tile of 64). 256 threads, 4x4 per thread.
// ---------------------------------------------------------------------------
#define QSTR 65
#define KSTR 68

__global__ void __launch_bounds__(256) attn_kernel(const float* __restrict__ present)
{
    extern __shared__ float sm[];
    float* Qs = sm;                    // [64][QSTR]  (row r, dim d)
    float* Ks = Qs + 64 * QSTR;        // [64][KSTR]  transposed: (dim d, col c)
    float* Vs = Ks + 64 * KSTR;        // [64][KSTR]  (row kr, dim d)
    float* Ps = Vs + 64 * KSTR;        // [64][KSTR]  (row r, col c)

    const int t = threadIdx.x;
    const int q0 = blockIdx.x * 64;
    const int h = blockIdx.y;
    const int b = blockIdx.z;

    const float* qptr = g_q + ((size_t)b * NHEAD + h) * SEQ * HDIM;
    const float* kptr = present + ((size_t)b * NHEAD + h) * SEQ * HDIM;
    const float* vptr = kptr + (size_t)BATCH * NHEAD * SEQ * HDIM;

    for (int idx = t; idx < 64 * 64; idx += 256) {
        int r = idx >> 6, d = idx & 63;
        Qs[r * QSTR + d] = qptr[(size_t)(q0 + r) * HDIM + d];
    }

    const int ty = t >> 4, tx = t & 15;
    float acc[4][4];
    float mi[4], li[4];
#pragma unroll
    for (int i = 0; i < 4; i++) {
        mi[i] = -1e30f;
        li[i] = 0.f;
#pragma unroll
        for (int j = 0; j < 4; j++) acc[i][j] = 0.f;
    }
    const float scale = 0.125f;  // 1/sqrt(64)

    for (int j0 = 0; j0 <= q0; j0 += 64) {
        __syncthreads();  // prev-iter P@V done (also: first iter pairs w/ Q load)
        for (int idx = t; idx < 64 * 64; idx += 256) {
            int c = idx >> 6, d = idx & 63;
            Ks[d * KSTR + c] = kptr[(size_t)(j0 + c) * HDIM + d];
            Vs[c * KSTR + d] = vptr[(size_t)(j0 + c) * HDIM + d];
        }
        __syncthreads();

        float s[4][4];
#pragma unroll
        for (int i = 0; i < 4; i++)
#pragma unroll
            for (int j = 0; j < 4; j++) s[i][j] = 0.f;

#pragma unroll 4
        for (int d = 0; d < 64; d++) {
            float qr[4];
#pragma unroll
            for (int i = 0; i < 4; i++) qr[i] = Qs[(ty * 4 + i) * QSTR + d];
            float4 kc = *(const float4*)(&Ks[d * KSTR + tx * 4]);
            float kcv[4] = {kc.x, kc.y, kc.z, kc.w};
#pragma unroll
            for (int i = 0; i < 4; i++)
#pragma unroll
                for (int j = 0; j < 4; j++) s[i][j] += qr[i] * kcv[j];
        }

        // causal mask + online softmax (stats replicated across 16-lane row group)
#pragma unroll
        for (int i = 0; i < 4; i++) {
            int qg = q0 + ty * 4 + i;
            float tmax = -1e30f;
#pragma unroll
            for (int j = 0; j < 4; j++) {
                int kg = j0 + tx * 4 + j;
                s[i][j] = (kg <= qg) ? s[i][j] * scale : -1e30f;
                tmax = fmaxf(tmax, s[i][j]);
            }
#pragma unroll
            for (int o = 8; o >= 1; o >>= 1)
                tmax = fmaxf(tmax, __shfl_xor_sync(0xffffffffu, tmax, o));
            float newm = fmaxf(mi[i], tmax);
            float corr = __expf(mi[i] - newm);
            float rsum = 0.f;
#pragma unroll
            for (int j = 0; j < 4; j++) {
                float p = __expf(s[i][j] - newm);
                s[i][j] = p;
                rsum += p;
            }
#pragma unroll
            for (int o = 8; o >= 1; o >>= 1)
                rsum += __shfl_xor_sync(0xffffffffu, rsum, o);
            li[i] = li[i] * corr + rsum;
            mi[i] = newm;
#pragma unroll
            for (int j = 0; j < 4; j++) acc[i][j] *= corr;
        }

#pragma unroll
        for (int i = 0; i < 4; i++) {
            float4 pv = make_float4(s[i][0], s[i][1], s[i][2], s[i][3]);
            *(float4*)(&Ps[(ty * 4 + i) * KSTR + tx * 4]) = pv;
        }
        __syncthreads();

#pragma unroll 4
        for (int kr = 0; kr < 64; kr++) {
            float pr[4];
#pragma unroll
            for (int i = 0; i < 4; i++) pr[i] = Ps[(ty * 4 + i) * KSTR + kr];
            float4 vv = *(const float4*)(&Vs[kr * KSTR + tx * 4]);
            float vvv[4] = {vv.x, vv.y, vv.z, vv.w};
#pragma unroll
            for (int i = 0; i < 4; i++)
#pragma unroll
                for (int j = 0; j < 4; j++) acc[i][j] += pr[i] * vvv[j];
        }
    }

    // epilogue: a[b, q0+r, h*64 + d] = acc / l
#pragma unroll
    for (int i = 0; i < 4; i++) {
        float inv = 1.f / li[i];
        int sg = q0 + ty * 4 + i;
        float* dst = g_a + ((size_t)b * SEQ + sg) * NXD + h * HDIM + tx * 4;
        float4 o = make_float4(acc[i][0] * inv, acc[i][1] * inv,
                               acc[i][2] * inv, acc[i][3] * inv);
        *(float4*)dst = o;
    }
}

// ---------------------------------------------------------------------------
// GEMM 2: out = a @ w_proj + b_proj.  A: [4096,1024], B: [1024,1024]
// ---------------------------------------------------------------------------
__global__ void __launch_bounds__(256) gemm_proj_kernel(
    const float* __restrict__ B, const float* __restrict__ bias,
    float* __restrict__ C)
{
    const int K = 1024, N = 1024;
    const float* A = g_a;
    __shared__ float As[8][128];
    __shared__ float Bs[8][128];
    const int t = threadIdx.x;
    const int bm = blockIdx.y * 128;
    const int bn = blockIdx.x * 128;
    const int arow = t >> 1, acol = (t & 1) * 4;
    const int brow = t >> 5, bcol = (t & 31) * 4;
    const int ty = t >> 4, tx = t & 15;

    float acc[8][8];
#pragma unroll
    for (int i = 0; i < 8; i++)
#pragma unroll
        for (int j = 0; j < 8; j++) acc[i][j] = 0.f;

    for (int k0 = 0; k0 < K; k0 += 8) {
        float4 av = *(const float4*)(A + (size_t)(bm + arow) * K + k0 + acol);
        As[acol + 0][arow] = av.x;
        As[acol + 1][arow] = av.y;
        As[acol + 2][arow] = av.z;
        As[acol + 3][arow] = av.w;
        *(float4*)(&Bs[brow][bcol]) =
            *(const float4*)(B + (size_t)(k0 + brow) * N + bn + bcol);
        __syncthreads();
#pragma unroll
        for (int kk = 0; kk < 8; kk++) {
            float ar[8], br[8];
            *(float4*)(ar)     = *(const float4*)(&As[kk][ty * 8]);
            *(float4*)(ar + 4) = *(const float4*)(&As[kk][ty * 8 + 4]);
            *(float4*)(br)     = *(const float4*)(&Bs[kk][tx * 8]);
            *(float4*)(br + 4) = *(const float4*)(&Bs[kk][tx * 8 + 4]);
#pragma unroll
            for (int i = 0; i < 8; i++)
#pragma unroll
                for (int j = 0; j < 8; j++) acc[i][j] += ar[i] * br[j];
        }
        __syncthreads();
    }

#pragma unroll
    for (int i = 0; i < 8; i++) {
        int m = bm + ty * 8 + i;
#pragma unroll
        for (int j = 0; j < 8; j += 4) {
            int n = bn + tx * 8 + j;
            float4 o = make_float4(acc[i][j] + bias[n],
                                   acc[i][j + 1] + bias[n + 1],
                                   acc[i][j + 2] + bias[n + 2],
                                   acc[i][j + 3] + bias[n + 3]);
            *(float4*)(C + (size_t)m * N + n) = o;
        }
    }
}

// ---------------------------------------------------------------------------
extern "C" void kernel_launch(void* const* d_in, const int* in_sizes, int n_in,
                              void* d_out, int out_size)
{
    const float* x      = (const float*)d_in[0];
    const float* w_attn = (const float*)d_in[1];
    const float* b_attn = (const float*)d_in[2];
    const float* w_proj = (const float*)d_in[3];
    const float* b_proj = (const float*)d_in[4];
    // d_in[5] = causal_bias (unused; causality computed analytically)

    float* out = (float*)d_out;
    float* present = out + (size_t)BATCH * SEQ * NXD;  // (2,B,NH,S,HD)

    dim3 g1(3072 / 128, 4096 / 128);
    gemm_qkv_kernel<<<g1, 256>>>(x, w_attn, b_attn, present);

    static int smem_set = 0;
    const int smem_bytes = (64 * QSTR + 3 * 64 * KSTR) * 4;  // 68,864
    if (!smem_set) {
        cudaFuncSetAttribute(attn_kernel,
                             cudaFuncAttributeMaxDynamicSharedMemorySize,
                             smem_bytes);
        smem_set = 1;
    }
    attn_kernel<<<dim3(SEQ / 64, NHEAD, BATCH), 256, smem_bytes>>>(present);

    dim3 g3(1024 / 128, 4096 / 128);
    gemm_proj_kernel<<<g3, 256>>>(w_proj, b_proj, out);
}

// round 3
// speedup vs baseline: 1.7412x; 1.7412x over previous
#include <cuda_runtime.h>
#include <cstdint>

#define BATCH 4
#define SEQ   1024
#define NXD   1024
#define NHEAD 16
#define HDIM  64
#define GK    1024

// Scratch (allocation-free rule: __device__ globals)
__device__ float g_q[(size_t)BATCH * NHEAD * SEQ * HDIM];   // [B,NH,S,HD]
__device__ float g_a[(size_t)BATCH * SEQ * NXD];            // [B,S,NX]
__device__ float g_wT_attn[(size_t)3 * NXD * NXD];          // [3072,1024]
__device__ float g_wT_proj[(size_t)NXD * NXD];              // [1024,1024]

__device__ __forceinline__ uint32_t smem_u32(const void* p) {
    uint32_t a;
    asm("{ .reg .u64 t; cvta.to.shared.u64 t, %1; cvt.u32.u64 %0, t; }"
        : "=r"(a) : "l"(p));
    return a;
}
__device__ __forceinline__ uint32_t cvt_tf32(float f) {
    uint32_t r;
    asm("cvt.rna.tf32.f32 %0, %1;" : "=r"(r) : "f"(f));
    return r;
}

// ---------------------------------------------------------------------------
// weight transpose: dst[C][R] = src[R][C]
// ---------------------------------------------------------------------------
__global__ void __launch_bounds__(256) transpose_kernel(
    const float* __restrict__ src, float* __restrict__ dst, int R, int C)
{
    __shared__ float tile[32][33];
    int c0 = blockIdx.x * 32, r0 = blockIdx.y * 32;
    int tx = threadIdx.x & 31, ty = threadIdx.x >> 5;
#pragma unroll
    for (int i = 0; i < 32; i += 8)
        tile[ty + i][tx] = src[(size_t)(r0 + ty + i) * C + c0 + tx];
    __syncthreads();
#pragma unroll
    for (int i = 0; i < 32; i += 8)
        dst[(size_t)(c0 + ty + i) * R + r0 + tx] = tile[tx][ty + i];
}

// ---------------------------------------------------------------------------
// tf32 mma.sync GEMM: C[m][n] = sum_k A[m][k] * BT[n][k] + bias[n]
// 256 threads, 128x128 tile, BK=32, cp.async double-buffered.
// Warp grid 2x4 (wm,wn); warp tile 64x32 = 4x4 m16n8k8 tiles.
// mode 0: scatter qkv to g_q/present.  mode 1: store to Cout.
// ---------------------------------------------------------------------------
#define TLD 36   // smem row stride (floats): conflict-free for both frag patterns

__global__ void __launch_bounds__(256) gemm_mma_kernel(
    const float* __restrict__ A, const float* __restrict__ BT,
    const float* __restrict__ bias, float* __restrict__ Cout,
    float* __restrict__ present, int mode)
{
    extern __shared__ float sm[];
    float* As[2] = { sm,              sm + 128 * TLD };
    float* Bs[2] = { sm + 2*128*TLD,  sm + 3*128*TLD };

    const int t = threadIdx.x;
    const int lane = t & 31, w = t >> 5;
    const int wm = w >> 2, wn = w & 3;
    const int qr = lane >> 2, qc = lane & 3;
    const int m0 = blockIdx.y * 128;
    const int n0 = blockIdx.x * 128;

    // global load coords: 4 chunks of float4 per thread per tile
    const int grow[4] = { (t + 0) >> 3, (t + 256) >> 3, (t + 512) >> 3, (t + 768) >> 3 };
    const int gc4 = (t & 7) * 4;

    float acc[4][4][4];
#pragma unroll
    for (int mt = 0; mt < 4; mt++)
#pragma unroll
        for (int nt = 0; nt < 4; nt++)
#pragma unroll
            for (int r = 0; r < 4; r++) acc[mt][nt][r] = 0.f;

    // prefetch tile 0
    {
        uint32_t sa = smem_u32(As[0]);
        uint32_t sb = smem_u32(Bs[0]);
#pragma unroll
        for (int i = 0; i < 4; i++) {
            int row = grow[i];
            uint32_t off = ((uint32_t)row * TLD + gc4) * 4;
            asm volatile("cp.async.cg.shared.global [%0], [%1], 16;"
                :: "r"(sa + off), "l"(A + (size_t)(m0 + row) * GK + gc4) : "memory");
            asm volatile("cp.async.cg.shared.global [%0], [%1], 16;"
                :: "r"(sb + off), "l"(BT + (size_t)(n0 + row) * GK + gc4) : "memory");
        }
        asm volatile("cp.async.commit_group;" ::: "memory");
    }

    for (int kb = 0; kb < 32; kb++) {
        const int buf = kb & 1;
        asm volatile("cp.async.wait_group 0;" ::: "memory");
        __syncthreads();

        if (kb < 31) {
            const int nb = (kb + 1) & 1;
            const int k0 = (kb + 1) * 32;
            uint32_t sa = smem_u32(As[nb]);
            uint32_t sb = smem_u32(Bs[nb]);
#pragma unroll
            for (int i = 0; i < 4; i++) {
                int row = grow[i];
                uint32_t off = ((uint32_t)row * TLD + gc4) * 4;
                asm volatile("cp.async.cg.shared.global [%0], [%1], 16;"
                    :: "r"(sa + off), "l"(A + (size_t)(m0 + row) * GK + k0 + gc4) : "memory");
                asm volatile("cp.async.cg.shared.global [%0], [%1], 16;"
                    :: "r"(sb + off), "l"(BT + (size_t)(n0 + row) * GK + k0 + gc4) : "memory");
            }
            asm volatile("cp.async.commit_group;" ::: "memory");
        }

        const float* ab = As[buf];
        const float* bb = Bs[buf];
#pragma unroll
        for (int ks = 0; ks < 4; ks++) {
            const int k = ks * 8;
            uint32_t af[4][4], bf[4][2];
#pragma unroll
            for (int mt = 0; mt < 4; mt++) {
                const float* ap = ab + (wm * 64 + mt * 16 + qr) * TLD + k + qc;
                af[mt][0] = cvt_tf32(ap[0]);
                af[mt][1] = cvt_tf32(ap[8 * TLD]);
                af[mt][2] = cvt_tf32(ap[4]);
                af[mt][3] = cvt_tf32(ap[8 * TLD + 4]);
            }
#pragma unroll
            for (int nt = 0; nt < 4; nt++) {
                const float* bp = bb + (wn * 32 + nt * 8 + qr) * TLD + k + qc;
                bf[nt][0] = cvt_tf32(bp[0]);
                bf[nt][1] = cvt_tf32(bp[4]);
            }
#pragma unroll
            for (int mt = 0; mt < 4; mt++)
#pragma unroll
                for (int nt = 0; nt < 4; nt++) {
                    asm volatile(
                        "mma.sync.aligned.m16n8k8.row.col.f32.tf32.tf32.f32 "
                        "{%0,%1,%2,%3}, {%4,%5,%6,%7}, {%8,%9}, {%0,%1,%2,%3};"
                        : "+f"(acc[mt][nt][0]), "+f"(acc[mt][nt][1]),
                          "+f"(acc[mt][nt][2]), "+f"(acc[mt][nt][3])
                        : "r"(af[mt][0]), "r"(af[mt][1]), "r"(af[mt][2]), "r"(af[mt][3]),
                          "r"(bf[nt][0]), "r"(bf[nt][1]));
                }
        }
        __syncthreads();
    }

    // epilogue
#pragma unroll
    for (int mt = 0; mt < 4; mt++) {
#pragma unroll
        for (int nt = 0; nt < 4; nt++) {
            int row = m0 + wm * 64 + mt * 16 + qr;
            int col = n0 + wn * 32 + nt * 8 + qc * 2;
            float bv0 = bias[col], bv1 = bias[col + 1];
            float v00 = acc[mt][nt][0] + bv0, v01 = acc[mt][nt][1] + bv1;
            float v10 = acc[mt][nt][2] + bv0, v11 = acc[mt][nt][3] + bv1;
            if (mode == 1) {
                *(float2*)(Cout + (size_t)row * NXD + col) = make_float2(v00, v01);
                *(float2*)(Cout + (size_t)(row + 8) * NXD + col) = make_float2(v10, v11);
            } else {
                int sec = col >> 10;
                int hn = col & 1023;
                int h = hn >> 6, d = hn & 63;
                int b0_ = row >> 10, s0_ = row & 1023;
                size_t i0 = (((size_t)b0_ * NHEAD + h) * SEQ + s0_) * HDIM + d;
                int b1_ = (row + 8) >> 10, s1_ = (row + 8) & 1023;
                size_t i1 = (((size_t)b1_ * NHEAD + h) * SEQ + s1_) * HDIM + d;
                float* base = (sec == 0) ? g_q
                            : (sec == 1) ? present
                            : present + (size_t)BATCH * NHEAD * SEQ * HDIM;
                *(float2*)(base + i0) = make_float2(v00, v01);
                *(float2*)(base + i1) = make_float2(v10, v11);
            }
        }
    }
}
#define GEMM_SMEM (4 * 128 * TLD * 4)   // 73,728 B

// ---------------------------------------------------------------------------
// Attention: flash-style, per (b,h,q_tile of 64). 256 threads, 4x4 per thread.
// ---------------------------------------------------------------------------
#define QSTR 65
#define KSTR 68

__global__ void __launch_bounds__(256) attn_kernel(const float* __restrict__ present)
{
    extern __shared__ float sm[];
    float* Qs = sm;
    float* Ks = Qs + 64 * QSTR;
    float* Vs = Ks + 64 * KSTR;
    float* Ps = Vs + 64 * KSTR;

    const int t = threadIdx.x;
    const int q0 = blockIdx.x * 64;
    const int h = blockIdx.y;
    const int b = blockIdx.z;

    const float* qptr = g_q + ((size_t)b * NHEAD + h) * SEQ * HDIM;
    const float* kptr = present + ((size_t)b * NHEAD + h) * SEQ * HDIM;
    const float* vptr = kptr + (size_t)BATCH * NHEAD * SEQ * HDIM;

    for (int idx = t; idx < 64 * 64; idx += 256) {
        int r = idx >> 6, d = idx & 63;
        Qs[r * QSTR + d] = qptr[(size_t)(q0 + r) * HDIM + d];
    }

    const int ty = t >> 4, tx = t & 15;
    float acc[4][4];
    float mi[4], li[4];
#pragma unroll
    for (int i = 0; i < 4; i++) {
        mi[i] = -1e30f;
        li[i] = 0.f;
#pragma unroll
        for (int j = 0; j < 4; j++) acc[i][j] = 0.f;
    }
    const float scale = 0.125f;

    for (int j0 = 0; j0 <= q0; j0 += 64) {
        __syncthreads();
        for (int idx = t; idx < 64 * 64; idx += 256) {
            int c = idx >> 6, d = idx & 63;
            Ks[d * KSTR + c] = kptr[(size_t)(j0 + c) * HDIM + d];
            Vs[c * KSTR + d] = vptr[(size_t)(j0 + c) * HDIM + d];
        }
        __syncthreads();

        float s[4][4];
#pragma unroll
        for (int i = 0; i < 4; i++)
#pragma unroll
            for (int j = 0; j < 4; j++) s[i][j] = 0.f;

#pragma unroll 4
        for (int d = 0; d < 64; d++) {
            float qr_[4];
#pragma unroll
            for (int i = 0; i < 4; i++) qr_[i] = Qs[(ty * 4 + i) * QSTR + d];
            float4 kc = *(const float4*)(&Ks[d * KSTR + tx * 4]);
            float kcv[4] = {kc.x, kc.y, kc.z, kc.w};
#pragma unroll
            for (int i = 0; i < 4; i++)
#pragma unroll
                for (int j = 0; j < 4; j++) s[i][j] += qr_[i] * kcv[j];
        }

#pragma unroll
        for (int i = 0; i < 4; i++) {
            int qg = q0 + ty * 4 + i;
            float tmax = -1e30f;
#pragma unroll
            for (int j = 0; j < 4; j++) {
                int kg = j0 + tx * 4 + j;
                s[i][j] = (kg <= qg) ? s[i][j] * scale : -1e30f;
                tmax = fmaxf(tmax, s[i][j]);
            }
#pragma unroll
            for (int o = 8; o >= 1; o >>= 1)
                tmax = fmaxf(tmax, __shfl_xor_sync(0xffffffffu, tmax, o));
            float newm = fmaxf(mi[i], tmax);
            float corr = __expf(mi[i] - newm);
            float rsum = 0.f;
#pragma unroll
            for (int j = 0; j < 4; j++) {
                float p = __expf(s[i][j] - newm);
                s[i][j] = p;
                rsum += p;
            }
#pragma unroll
            for (int o = 8; o >= 1; o >>= 1)
                rsum += __shfl_xor_sync(0xffffffffu, rsum, o);
            li[i] = li[i] * corr + rsum;
            mi[i] = newm;
#pragma unroll
            for (int j = 0; j < 4; j++) acc[i][j] *= corr;
        }

#pragma unroll
        for (int i = 0; i < 4; i++) {
            float4 pv = make_float4(s[i][0], s[i][1], s[i][2], s[i][3]);
            *(float4*)(&Ps[(ty * 4 + i) * KSTR + tx * 4]) = pv;
        }
        __syncthreads();

#pragma unroll 4
        for (int kr = 0; kr < 64; kr++) {
            float pr[4];
#pragma unroll
            for (int i = 0; i < 4; i++) pr[i] = Ps[(ty * 4 + i) * KSTR + kr];
            float4 vv = *(const float4*)(&Vs[kr * KSTR + tx * 4]);
            float vvv[4] = {vv.x, vv.y, vv.z, vv.w};
#pragma unroll
            for (int i = 0; i < 4; i++)
#pragma unroll
                for (int j = 0; j < 4; j++) acc[i][j] += pr[i] * vvv[j];
        }
    }

#pragma unroll
    for (int i = 0; i < 4; i++) {
        float inv = 1.f / li[i];
        int sg = q0 + ty * 4 + i;
        float* dst = g_a + ((size_t)b * SEQ + sg) * NXD + h * HDIM + tx * 4;
        float4 o = make_float4(acc[i][0] * inv, acc[i][1] * inv,
                               acc[i][2] * inv, acc[i][3] * inv);
        *(float4*)dst = o;
    }
}

// ---------------------------------------------------------------------------
extern "C" void kernel_launch(void* const* d_in, const int* in_sizes, int n_in,
                              void* d_out, int out_size)
{
    const float* x      = (const float*)d_in[0];
    const float* w_attn = (const float*)d_in[1];
    const float* b_attn = (const float*)d_in[2];
    const float* w_proj = (const float*)d_in[3];
    const float* b_proj = (const float*)d_in[4];

    float* out = (float*)d_out;
    float* present = out + (size_t)BATCH * SEQ * NXD;  // (2,B,NH,S,HD)

    cudaFuncSetAttribute(gemm_mma_kernel,
                         cudaFuncAttributeMaxDynamicSharedMemorySize, GEMM_SMEM);
    const int attn_smem = (64 * QSTR + 3 * 64 * KSTR) * 4;
    cudaFuncSetAttribute(attn_kernel,
                         cudaFuncAttributeMaxDynamicSharedMemorySize, attn_smem);

    float* wT_attn;  cudaGetSymbolAddress((void**)&wT_attn, g_wT_attn);
    float* wT_proj;  cudaGetSymbolAddress((void**)&wT_proj, g_wT_proj);
    float* a_ptr;    cudaGetSymbolAddress((void**)&a_ptr, g_a);

    transpose_kernel<<<dim3(3 * NXD / 32, NXD / 32), 256>>>(w_attn, wT_attn, NXD, 3 * NXD);
    transpose_kernel<<<dim3(NXD / 32, NXD / 32), 256>>>(w_proj, wT_proj, NXD, NXD);

    gemm_mma_kernel<<<dim3(3 * NXD / 128, BATCH * SEQ / 128), 256, GEMM_SMEM>>>(
        x, wT_attn, b_attn, nullptr, present, 0);

    attn_kernel<<<dim3(SEQ / 64, NHEAD, BATCH), 256, attn_smem>>>(present);

    gemm_mma_kernel<<<dim3(NXD / 128, BATCH * SEQ / 128), 256, GEMM_SMEM>>>(
        a_ptr, wT_proj, b_proj, out, nullptr, 1);
}

// round 4
// speedup vs baseline: 2.2161x; 1.2727x over previous
#include <cuda_runtime.h>
#include <cstdint>

#define BATCH 4
#define SEQ   1024
#define NXD   1024
#define NHEAD 16
#define HDIM  64
#define GK    1024

// Scratch (allocation-free rule: __device__ globals)
__device__ float g_q[(size_t)BATCH * NHEAD * SEQ * HDIM];   // [B,NH,S,HD]
__device__ float g_a[(size_t)BATCH * SEQ * NXD];            // [B,S,NX]
__device__ float g_wT_attn[(size_t)3 * NXD * NXD];          // [3072,1024]
__device__ float g_wT_proj[(size_t)NXD * NXD];              // [1024,1024]

__device__ __forceinline__ uint32_t smem_u32(const void* p) {
    uint32_t a;
    asm("{ .reg .u64 t; cvta.to.shared.u64 t, %1; cvt.u32.u64 %0, t; }"
        : "=r"(a) : "l"(p));
    return a;
}
__device__ __forceinline__ uint32_t cvt_tf32(float f) {
    uint32_t r;
    asm("cvt.rna.tf32.f32 %0, %1;" : "=r"(r) : "f"(f));
    return r;
}
__device__ __forceinline__ void mma_tf32(float* d,
    uint32_t a0, uint32_t a1, uint32_t a2, uint32_t a3,
    uint32_t b0, uint32_t b1)
{
    asm volatile(
        "mma.sync.aligned.m16n8k8.row.col.f32.tf32.tf32.f32 "
        "{%0,%1,%2,%3}, {%4,%5,%6,%7}, {%8,%9}, {%0,%1,%2,%3};"
        : "+f"(d[0]), "+f"(d[1]), "+f"(d[2]), "+f"(d[3])
        : "r"(a0), "r"(a1), "r"(a2), "r"(a3), "r"(b0), "r"(b1));
}

// ---------------------------------------------------------------------------
// weight transpose: dst[C][R] = src[R][C]
// ---------------------------------------------------------------------------
__global__ void __launch_bounds__(256) transpose_kernel(
    const float* __restrict__ src, float* __restrict__ dst, int R, int C)
{
    __shared__ float tile[32][33];
    int c0 = blockIdx.x * 32, r0 = blockIdx.y * 32;
    int tx = threadIdx.x & 31, ty = threadIdx.x >> 5;
#pragma unroll
    for (int i = 0; i < 32; i += 8)
        tile[ty + i][tx] = src[(size_t)(r0 + ty + i) * C + c0 + tx];
    __syncthreads();
#pragma unroll
    for (int i = 0; i < 32; i += 8)
        dst[(size_t)(c0 + ty + i) * R + r0 + tx] = tile[tx][ty + i];
}

// ---------------------------------------------------------------------------
// tf32 mma.sync GEMM (unchanged from R3, verified)
// ---------------------------------------------------------------------------
#define TLD 36

__global__ void __launch_bounds__(256) gemm_mma_kernel(
    const float* __restrict__ A, const float* __restrict__ BT,
    const float* __restrict__ bias, float* __restrict__ Cout,
    float* __restrict__ present, int mode)
{
    extern __shared__ float sm[];
    float* As[2] = { sm,              sm + 128 * TLD };
    float* Bs[2] = { sm + 2*128*TLD,  sm + 3*128*TLD };

    const int t = threadIdx.x;
    const int lane = t & 31, w = t >> 5;
    const int wm = w >> 2, wn = w & 3;
    const int qr = lane >> 2, qc = lane & 3;
    const int m0 = blockIdx.y * 128;
    const int n0 = blockIdx.x * 128;

    const int grow[4] = { (t + 0) >> 3, (t + 256) >> 3, (t + 512) >> 3, (t + 768) >> 3 };
    const int gc4 = (t & 7) * 4;

    float acc[4][4][4];
#pragma unroll
    for (int mt = 0; mt < 4; mt++)
#pragma unroll
        for (int nt = 0; nt < 4; nt++)
#pragma unroll
            for (int r = 0; r < 4; r++) acc[mt][nt][r] = 0.f;

    {
        uint32_t sa = smem_u32(As[0]);
        uint32_t sb = smem_u32(Bs[0]);
#pragma unroll
        for (int i = 0; i < 4; i++) {
            int row = grow[i];
            uint32_t off = ((uint32_t)row * TLD + gc4) * 4;
            asm volatile("cp.async.cg.shared.global [%0], [%1], 16;"
                :: "r"(sa + off), "l"(A + (size_t)(m0 + row) * GK + gc4) : "memory");
            asm volatile("cp.async.cg.shared.global [%0], [%1], 16;"
                :: "r"(sb + off), "l"(BT + (size_t)(n0 + row) * GK + gc4) : "memory");
        }
        asm volatile("cp.async.commit_group;" ::: "memory");
    }

    for (int kb = 0; kb < 32; kb++) {
        const int buf = kb & 1;
        asm volatile("cp.async.wait_group 0;" ::: "memory");
        __syncthreads();

        if (kb < 31) {
            const int nb = (kb + 1) & 1;
            const int k0 = (kb + 1) * 32;
            uint32_t sa = smem_u32(As[nb]);
            uint32_t sb = smem_u32(Bs[nb]);
#pragma unroll
            for (int i = 0; i < 4; i++) {
                int row = grow[i];
                uint32_t off = ((uint32_t)row * TLD + gc4) * 4;
                asm volatile("cp.async.cg.shared.global [%0], [%1], 16;"
                    :: "r"(sa + off), "l"(A + (size_t)(m0 + row) * GK + k0 + gc4) : "memory");
                asm volatile("cp.async.cg.shared.global [%0], [%1], 16;"
                    :: "r"(sb + off), "l"(BT + (size_t)(n0 + row) * GK + k0 + gc4) : "memory");
            }
            asm volatile("cp.async.commit_group;" ::: "memory");
        }

        const float* ab = As[buf];
        const float* bb = Bs[buf];
#pragma unroll
        for (int ks = 0; ks < 4; ks++) {
            const int k = ks * 8;
            uint32_t af[4][4], bf[4][2];
#pragma unroll
            for (int mt = 0; mt < 4; mt++) {
                const float* ap = ab + (wm * 64 + mt * 16 + qr) * TLD + k + qc;
                af[mt][0] = cvt_tf32(ap[0]);
                af[mt][1] = cvt_tf32(ap[8 * TLD]);
                af[mt][2] = cvt_tf32(ap[4]);
                af[mt][3] = cvt_tf32(ap[8 * TLD + 4]);
            }
#pragma unroll
            for (int nt = 0; nt < 4; nt++) {
                const float* bp = bb + (wn * 32 + nt * 8 + qr) * TLD + k + qc;
                bf[nt][0] = cvt_tf32(bp[0]);
                bf[nt][1] = cvt_tf32(bp[4]);
            }
#pragma unroll
            for (int mt = 0; mt < 4; mt++)
#pragma unroll
                for (int nt = 0; nt < 4; nt++)
                    mma_tf32(acc[mt][nt], af[mt][0], af[mt][1], af[mt][2], af[mt][3],
                             bf[nt][0], bf[nt][1]);
        }
        __syncthreads();
    }

#pragma unroll
    for (int mt = 0; mt < 4; mt++) {
#pragma unroll
        for (int nt = 0; nt < 4; nt++) {
            int row = m0 + wm * 64 + mt * 16 + qr;
            int col = n0 + wn * 32 + nt * 8 + qc * 2;
            float bv0 = bias[col], bv1 = bias[col + 1];
            float v00 = acc[mt][nt][0] + bv0, v01 = acc[mt][nt][1] + bv1;
            float v10 = acc[mt][nt][2] + bv0, v11 = acc[mt][nt][3] + bv1;
            if (mode == 1) {
                *(float2*)(Cout + (size_t)row * NXD + col) = make_float2(v00, v01);
                *(float2*)(Cout + (size_t)(row + 8) * NXD + col) = make_float2(v10, v11);
            } else {
                int sec = col >> 10;
                int hn = col & 1023;
                int h = hn >> 6, d = hn & 63;
                int b0_ = row >> 10, s0_ = row & 1023;
                size_t i0 = (((size_t)b0_ * NHEAD + h) * SEQ + s0_) * HDIM + d;
                int b1_ = (row + 8) >> 10, s1_ = (row + 8) & 1023;
                size_t i1 = (((size_t)b1_ * NHEAD + h) * SEQ + s1_) * HDIM + d;
                float* base = (sec == 0) ? g_q
                            : (sec == 1) ? present
                            : present + (size_t)BATCH * NHEAD * SEQ * HDIM;
                *(float2*)(base + i0) = make_float2(v00, v01);
                *(float2*)(base + i1) = make_float2(v10, v11);
            }
        }
    }
}
#define GEMM_SMEM (4 * 128 * TLD * 4)

// ---------------------------------------------------------------------------
// Attention via tf32 mma.sync, FA2 fragment softmax.
// Block: 128 q rows x (b,h). 8 warps, warp w owns q rows [w*16, w*16+16).
// K-tiles of 64. Smem tiles pre-converted to tf32, stride 68 (conflict-free).
// ---------------------------------------------------------------------------
#define ALD 68
#define ATTN_SMEM ((128*ALD + 64*ALD + 64*ALD + 128*ALD) * 4)   // 104,448 B

__global__ void __launch_bounds__(256, 1) attn_mma_kernel(const float* __restrict__ present)
{
    extern __shared__ uint32_t usm[];
    uint32_t* Qs = usm;                    // [128][ALD] tf32, q-scale folded
    uint32_t* Ks = Qs + 128 * ALD;         // [64][ALD]  (kpos, d)
    uint32_t* Vs = Ks + 64 * ALD;          // [64][ALD]  transposed (d, kpos)
    uint32_t* Ps = Vs + 64 * ALD;          // [128][ALD] P staging / O staging

    const int t = threadIdx.x;
    const int lane = t & 31, w = t >> 5;
    const int qr = lane >> 2, qc = lane & 3;
    const int q0 = blockIdx.x * 128;
    const int h = blockIdx.y;
    const int b = blockIdx.z;

    const float* qptr = g_q + ((size_t)b * NHEAD + h) * SEQ * HDIM;
    const float* kptr = present + ((size_t)b * NHEAD + h) * SEQ * HDIM;
    const float* vptr = kptr + (size_t)BATCH * NHEAD * SEQ * HDIM;

    // load Q tile once: tf32, softmax scale folded in
    for (int idx = t; idx < 128 * 64; idx += 256) {
        int r = idx >> 6, d = idx & 63;
        Qs[r * ALD + d] = cvt_tf32(qptr[(size_t)(q0 + r) * HDIM + d] * 0.125f);
    }

    float oacc[8][4];
#pragma unroll
    for (int nt = 0; nt < 8; nt++)
#pragma unroll
        for (int r = 0; r < 4; r++) oacc[nt][r] = 0.f;
    float m0 = -1e30f, m1 = -1e30f, l0 = 0.f, l1 = 0.f;

    const int wrow = w * 16;               // warp's first q row (block-local)
    const int qg0 = q0 + wrow + qr;        // global q row of fragment row 0
    const int qg1 = qg0 + 8;
    const int qmax = q0 + wrow + 15;
    const int nj = blockIdx.x * 2 + 2;     // #64-wide K-tiles

    for (int jt = 0; jt < nj; jt++) {
        const int j0 = jt * 64;
        __syncthreads();
        for (int idx = t; idx < 64 * 64; idx += 256) {
            int c = idx >> 6, d = idx & 63;
            float kv = kptr[(size_t)(j0 + c) * HDIM + d];
            float vv = vptr[(size_t)(j0 + c) * HDIM + d];
            Ks[c * ALD + d] = cvt_tf32(kv);
            Vs[d * ALD + c] = cvt_tf32(vv);
        }
        __syncthreads();
        if (j0 > qmax) continue;           // fully masked for this warp

        // ---- S = Q @ K^T (warp: 16 x 64) ----
        float sacc[8][4];
#pragma unroll
        for (int nt = 0; nt < 8; nt++)
#pragma unroll
            for (int r = 0; r < 4; r++) sacc[nt][r] = 0.f;

#pragma unroll
        for (int ks = 0; ks < 8; ks++) {
            const int k = ks * 8;
            uint32_t a0 = Qs[(wrow + qr) * ALD + k + qc];
            uint32_t a1 = Qs[(wrow + qr + 8) * ALD + k + qc];
            uint32_t a2 = Qs[(wrow + qr) * ALD + k + qc + 4];
            uint32_t a3 = Qs[(wrow + qr + 8) * ALD + k + qc + 4];
#pragma unroll
            for (int nt = 0; nt < 8; nt++) {
                uint32_t b0 = Ks[(nt * 8 + qr) * ALD + k + qc];
                uint32_t b1 = Ks[(nt * 8 + qr) * ALD + k + qc + 4];
                mma_tf32(sacc[nt], a0, a1, a2, a3, b0, b1);
            }
        }

        // ---- causal mask + row max ----
        float rx0 = -1e30f, rx1 = -1e30f;
#pragma unroll
        for (int nt = 0; nt < 8; nt++) {
            int kg = j0 + nt * 8 + qc * 2;
            if (kg > qg0)     sacc[nt][0] = -1e30f;
            if (kg + 1 > qg0) sacc[nt][1] = -1e30f;
            if (kg > qg1)     sacc[nt][2] = -1e30f;
            if (kg + 1 > qg1) sacc[nt][3] = -1e30f;
            rx0 = fmaxf(rx0, fmaxf(sacc[nt][0], sacc[nt][1]));
            rx1 = fmaxf(rx1, fmaxf(sacc[nt][2], sacc[nt][3]));
        }
        rx0 = fmaxf(rx0, __shfl_xor_sync(0xffffffffu, rx0, 1));
        rx0 = fmaxf(rx0, __shfl_xor_sync(0xffffffffu, rx0, 2));
        rx1 = fmaxf(rx1, __shfl_xor_sync(0xffffffffu, rx1, 1));
        rx1 = fmaxf(rx1, __shfl_xor_sync(0xffffffffu, rx1, 2));

        float nm0 = fmaxf(m0, rx0), nm1 = fmaxf(m1, rx1);
        float cr0 = __expf(m0 - nm0), cr1 = __expf(m1 - nm1);

        // ---- exp, row sum, stage P (tf32) ----
        float rs0 = 0.f, rs1 = 0.f;
#pragma unroll
        for (int nt = 0; nt < 8; nt++) {
            float p00 = __expf(sacc[nt][0] - nm0);
            float p01 = __expf(sacc[nt][1] - nm0);
            float p10 = __expf(sacc[nt][2] - nm1);
            float p11 = __expf(sacc[nt][3] - nm1);
            rs0 += p00 + p01;
            rs1 += p10 + p11;
            uint32_t col = nt * 8 + qc * 2;
            *(uint2*)&Ps[(wrow + qr) * ALD + col]     = make_uint2(cvt_tf32(p00), cvt_tf32(p01));
            *(uint2*)&Ps[(wrow + qr + 8) * ALD + col] = make_uint2(cvt_tf32(p10), cvt_tf32(p11));
        }
        rs0 += __shfl_xor_sync(0xffffffffu, rs0, 1);
        rs0 += __shfl_xor_sync(0xffffffffu, rs0, 2);
        rs1 += __shfl_xor_sync(0xffffffffu, rs1, 1);
        rs1 += __shfl_xor_sync(0xffffffffu, rs1, 2);

        l0 = l0 * cr0 + rs0;  m0 = nm0;
        l1 = l1 * cr1 + rs1;  m1 = nm1;
#pragma unroll
        for (int nt = 0; nt < 8; nt++) {
            oacc[nt][0] *= cr0;  oacc[nt][1] *= cr0;
            oacc[nt][2] *= cr1;  oacc[nt][3] *= cr1;
        }
        __syncwarp();

        // ---- O += P @ V (warp: 16 x 64, K=64) ----
#pragma unroll
        for (int ks = 0; ks < 8; ks++) {
            const int k = ks * 8;
            uint32_t a0 = Ps[(wrow + qr) * ALD + k + qc];
            uint32_t a1 = Ps[(wrow + qr + 8) * ALD + k + qc];
            uint32_t a2 = Ps[(wrow + qr) * ALD + k + qc + 4];
            uint32_t a3 = Ps[(wrow + qr + 8) * ALD + k + qc + 4];
#pragma unroll
            for (int nt = 0; nt < 8; nt++) {
                uint32_t b0 = Vs[(nt * 8 + qr) * ALD + k + qc];
                uint32_t b1 = Vs[(nt * 8 + qr) * ALD + k + qc + 4];
                mma_tf32(oacc[nt], a0, a1, a2, a3, b0, b1);
            }
        }
        __syncwarp();   // Ps reads done before next iter overwrites
    }

    // ---- epilogue: normalize, stage to smem, coalesced write ----
    __syncthreads();
    float* Pf = (float*)Ps;
    float inv0 = 1.f / l0, inv1 = 1.f / l1;
#pragma unroll
    for (int nt = 0; nt < 8; nt++) {
        uint32_t col = nt * 8 + qc * 2;
        *(float2*)&Pf[(wrow + qr) * ALD + col] =
            make_float2(oacc[nt][0] * inv0, oacc[nt][1] * inv0);
        *(float2*)&Pf[(wrow + qr + 8) * ALD + col] =
            make_float2(oacc[nt][2] * inv1, oacc[nt][3] * inv1);
    }
    __syncthreads();
    for (int idx = t; idx < 128 * 16; idx += 256) {
        int row = idx >> 4, ch = idx & 15;
        float4 v = *(float4*)&Pf[row * ALD + ch * 4];
        *(float4*)(g_a + ((size_t)b * SEQ + q0 + row) * NXD + h * HDIM + ch * 4) = v;
    }
}

// ---------------------------------------------------------------------------
extern "C" void kernel_launch(void* const* d_in, const int* in_sizes, int n_in,
                              void* d_out, int out_size)
{
    const float* x      = (const float*)d_in[0];
    const float* w_attn = (const float*)d_in[1];
    const float* b_attn = (const float*)d_in[2];
    const float* w_proj = (const float*)d_in[3];
    const float* b_proj = (const float*)d_in[4];

    float* out = (float*)d_out;
    float* present = out + (size_t)BATCH * SEQ * NXD;  // (2,B,NH,S,HD)

    cudaFuncSetAttribute(gemm_mma_kernel,
                         cudaFuncAttributeMaxDynamicSharedMemorySize, GEMM_SMEM);
    cudaFuncSetAttribute(attn_mma_kernel,
                         cudaFuncAttributeMaxDynamicSharedMemorySize, ATTN_SMEM);

    float* wT_attn;  cudaGetSymbolAddress((void**)&wT_attn, g_wT_attn);
    float* wT_proj;  cudaGetSymbolAddress((void**)&wT_proj, g_wT_proj);
    float* a_ptr;    cudaGetSymbolAddress((void**)&a_ptr, g_a);

    transpose_kernel<<<dim3(3 * NXD / 32, NXD / 32), 256>>>(w_attn, wT_attn, NXD, 3 * NXD);
    transpose_kernel<<<dim3(NXD / 32, NXD / 32), 256>>>(w_proj, wT_proj, NXD, NXD);

    gemm_mma_kernel<<<dim3(3 * NXD / 128, BATCH * SEQ / 128), 256, GEMM_SMEM>>>(
        x, wT_attn, b_attn, nullptr, present, 0);

    attn_mma_kernel<<<dim3(SEQ / 128, NHEAD, BATCH), 256, ATTN_SMEM>>>(present);

    gemm_mma_kernel<<<dim3(NXD / 128, BATCH * SEQ / 128), 256, GEMM_SMEM>>>(
        a_ptr, wT_proj, b_proj, out, nullptr, 1);
}

// round 5
// speedup vs baseline: 2.7233x; 1.2289x over previous
#include <cuda_runtime.h>
#include <cstdint>

#define BATCH 4
#define SEQ   1024
#define NXD   1024
#define NHEAD 16
#define HDIM  64
#define GK    1024

// Scratch (allocation-free rule: __device__ globals)
__device__ float g_q[(size_t)BATCH * NHEAD * SEQ * HDIM];   // [B,NH,S,HD] (pre-scaled by 1/8)
__device__ float g_a[(size_t)BATCH * SEQ * NXD];            // [B,S,NX]
__device__ float g_wT_attn[(size_t)3 * NXD * NXD];          // [3072,1024]
__device__ float g_wT_proj[(size_t)NXD * NXD];              // [1024,1024]

__device__ __forceinline__ uint32_t smem_u32(const void* p) {
    uint32_t a;
    asm("{ .reg .u64 t; cvta.to.shared.u64 t, %1; cvt.u32.u64 %0, t; }"
        : "=r"(a) : "l"(p));
    return a;
}
__device__ __forceinline__ uint32_t cvt_tf32(float f) {
    uint32_t r;
    asm("cvt.rna.tf32.f32 %0, %1;" : "=r"(r) : "f"(f));
    return r;
}
__device__ __forceinline__ void cp16(uint32_t dst, const void* src) {
    asm volatile("cp.async.cg.shared.global [%0], [%1], 16;"
                 :: "r"(dst), "l"(src) : "memory");
}
__device__ __forceinline__ void cp_commit() {
    asm volatile("cp.async.commit_group;" ::: "memory");
}
__device__ __forceinline__ void mma_tf32(float* d,
    uint32_t a0, uint32_t a1, uint32_t a2, uint32_t a3,
    uint32_t b0, uint32_t b1)
{
    asm volatile(
        "mma.sync.aligned.m16n8k8.row.col.f32.tf32.tf32.f32 "
        "{%0,%1,%2,%3}, {%4,%5,%6,%7}, {%8,%9}, {%0,%1,%2,%3};"
        : "+f"(d[0]), "+f"(d[1]), "+f"(d[2]), "+f"(d[3])
        : "r"(a0), "r"(a1), "r"(a2), "r"(a3), "r"(b0), "r"(b1));
}

// ---------------------------------------------------------------------------
// weight transpose: dst[C][R] = src[R][C]
// ---------------------------------------------------------------------------
__global__ void __launch_bounds__(256) transpose_kernel(
    const float* __restrict__ src, float* __restrict__ dst, int R, int C)
{
    __shared__ float tile[32][33];
    int c0 = blockIdx.x * 32, r0 = blockIdx.y * 32;
    int tx = threadIdx.x & 31, ty = threadIdx.x >> 5;
#pragma unroll
    for (int i = 0; i < 32; i += 8)
        tile[ty + i][tx] = src[(size_t)(r0 + ty + i) * C + c0 + tx];
    __syncthreads();
#pragma unroll
    for (int i = 0; i < 32; i += 8)
        dst[(size_t)(c0 + ty + i) * R + r0 + tx] = tile[tx][ty + i];
}

// ---------------------------------------------------------------------------
// tf32 mma.sync GEMM, 3-stage cp.async pipeline.
// C[m][n] = sum_k A[m][k] * BT[n][k] + bias[n]
// mode 0: scatter qkv (q scaled by 0.125).  mode 1: store to Cout.
// ---------------------------------------------------------------------------
#define TLD 36
#define GEMM_SMEM (3 * 2 * 128 * TLD * 4)   // 110,592 B

__global__ void __launch_bounds__(256) gemm_mma_kernel(
    const float* __restrict__ A, const float* __restrict__ BT,
    const float* __restrict__ bias, float* __restrict__ Cout,
    float* __restrict__ present, int mode)
{
    extern __shared__ float sm[];

    const int t = threadIdx.x;
    const int lane = t & 31, w = t >> 5;
    const int wm = w >> 2, wn = w & 3;
    const int qr = lane >> 2, qc = lane & 3;
    const int m0 = blockIdx.y * 128;
    const int n0 = blockIdx.x * 128;

    const int grow[4] = { (t + 0) >> 3, (t + 256) >> 3, (t + 512) >> 3, (t + 768) >> 3 };
    const int gc4 = (t & 7) * 4;

    uint32_t sa_[3], sb_[3];
#pragma unroll
    for (int s = 0; s < 3; s++) {
        sa_[s] = smem_u32(sm + s * 2 * 128 * TLD);
        sb_[s] = sa_[s] + 128 * TLD * 4;
    }

    float acc[4][4][4];
#pragma unroll
    for (int mt = 0; mt < 4; mt++)
#pragma unroll
        for (int nt = 0; nt < 4; nt++)
#pragma unroll
            for (int r = 0; r < 4; r++) acc[mt][nt][r] = 0.f;

    // prefetch stages 0,1
#pragma unroll
    for (int s = 0; s < 2; s++) {
        const int k0 = s * 32;
#pragma unroll
        for (int i = 0; i < 4; i++) {
            int row = grow[i];
            uint32_t off = ((uint32_t)row * TLD + gc4) * 4;
            cp16(sa_[s] + off, A + (size_t)(m0 + row) * GK + k0 + gc4);
            cp16(sb_[s] + off, BT + (size_t)(n0 + row) * GK + k0 + gc4);
        }
        cp_commit();
    }

    for (int kb = 0; kb < 32; kb++) {
        if (kb < 30)
            asm volatile("cp.async.wait_group 1;" ::: "memory");
        else
            asm volatile("cp.async.wait_group 0;" ::: "memory");
        __syncthreads();

        if (kb + 2 < 32) {
            const int s = (kb + 2) % 3;
            const int k0 = (kb + 2) * 32;
#pragma unroll
            for (int i = 0; i < 4; i++) {
                int row = grow[i];
                uint32_t off = ((uint32_t)row * TLD + gc4) * 4;
                cp16(sa_[s] + off, A + (size_t)(m0 + row) * GK + k0 + gc4);
                cp16(sb_[s] + off, BT + (size_t)(n0 + row) * GK + k0 + gc4);
            }
            cp_commit();
        }

        const float* ab = sm + (kb % 3) * 2 * 128 * TLD;
        const float* bb = ab + 128 * TLD;
#pragma unroll
        for (int ks = 0; ks < 4; ks++) {
            const int k = ks * 8;
            uint32_t af[4][4], bf[4][2];
#pragma unroll
            for (int mt = 0; mt < 4; mt++) {
                const float* ap = ab + (wm * 64 + mt * 16 + qr) * TLD + k + qc;
                af[mt][0] = cvt_tf32(ap[0]);
                af[mt][1] = cvt_tf32(ap[8 * TLD]);
                af[mt][2] = cvt_tf32(ap[4]);
                af[mt][3] = cvt_tf32(ap[8 * TLD + 4]);
            }
#pragma unroll
            for (int nt = 0; nt < 4; nt++) {
                const float* bp = bb + (wn * 32 + nt * 8 + qr) * TLD + k + qc;
                bf[nt][0] = cvt_tf32(bp[0]);
                bf[nt][1] = cvt_tf32(bp[4]);
            }
#pragma unroll
            for (int mt = 0; mt < 4; mt++)
#pragma unroll
                for (int nt = 0; nt < 4; nt++)
                    mma_tf32(acc[mt][nt], af[mt][0], af[mt][1], af[mt][2], af[mt][3],
                             bf[nt][0], bf[nt][1]);
        }
    }

#pragma unroll
    for (int mt = 0; mt < 4; mt++) {
#pragma unroll
        for (int nt = 0; nt < 4; nt++) {
            int row = m0 + wm * 64 + mt * 16 + qr;
            int col = n0 + wn * 32 + nt * 8 + qc * 2;
            float bv0 = bias[col], bv1 = bias[col + 1];
            float v00 = acc[mt][nt][0] + bv0, v01 = acc[mt][nt][1] + bv1;
            float v10 = acc[mt][nt][2] + bv0, v11 = acc[mt][nt][3] + bv1;
            if (mode == 1) {
                *(float2*)(Cout + (size_t)row * NXD + col) = make_float2(v00, v01);
                *(float2*)(Cout + (size_t)(row + 8) * NXD + col) = make_float2(v10, v11);
            } else {
                int sec = col >> 10;
                int hn = col & 1023;
                int h = hn >> 6, d = hn & 63;
                if (sec == 0) {   // q: fold softmax scale
                    v00 *= 0.125f; v01 *= 0.125f; v10 *= 0.125f; v11 *= 0.125f;
                }
                int b0_ = row >> 10, s0_ = row & 1023;
                size_t i0 = (((size_t)b0_ * NHEAD + h) * SEQ + s0_) * HDIM + d;
                int b1_ = (row + 8) >> 10, s1_ = (row + 8) & 1023;
                size_t i1 = (((size_t)b1_ * NHEAD + h) * SEQ + s1_) * HDIM + d;
                float* base = (sec == 0) ? g_q
                            : (sec == 1) ? present
                            : present + (size_t)BATCH * NHEAD * SEQ * HDIM;
                *(float2*)(base + i0) = make_float2(v00, v01);
                *(float2*)(base + i1) = make_float2(v10, v11);
            }
        }
    }
}

// ---------------------------------------------------------------------------
// Attention via tf32 mma.sync, FA2 fragment softmax, cp.async double-buffered
// K/V tiles. Block: 128 q rows x (b,h), 8 warps (16 q rows each), K-tiles 64.
// Smem fp32, stride 68; cvt to tf32 at fragment read.
// V stored (kpos, d) — P@V B-frag reads are ≤2-way conflicted.
// ---------------------------------------------------------------------------
#define ALD 68
// floats: Q 128*ALD + K 2*64*ALD + V 2*64*ALD + P 128*ALD = 512*ALD
#define ATTN_SMEM (512 * ALD * 4)   // 139,264 B

__global__ void __launch_bounds__(256, 1) attn_mma_kernel(const float* __restrict__ present)
{
    extern __shared__ float sma[];
    float* Qs = sma;                          // [128][ALD] fp32 (pre-scaled q)
    float* Ksb = Qs + 128 * ALD;              // 2 x [64][ALD] (kpos, d)
    float* Vsb = Ksb + 2 * 64 * ALD;          // 2 x [64][ALD] (kpos, d)
    uint32_t* Ps = (uint32_t*)(Vsb + 2 * 64 * ALD);  // [128][ALD] tf32 P / fp32 O

    const int t = threadIdx.x;
    const int lane = t & 31, w = t >> 5;
    const int qr = lane >> 2, qc = lane & 3;
    const int q0 = blockIdx.x * 128;
    const int h = blockIdx.y;
    const int b = blockIdx.z;

    const float* qptr = g_q + ((size_t)b * NHEAD + h) * SEQ * HDIM;
    const float* kptr = present + ((size_t)b * NHEAD + h) * SEQ * HDIM;
    const float* vptr = kptr + (size_t)BATCH * NHEAD * SEQ * HDIM;

    const uint32_t qs_a = smem_u32(Qs);
    const uint32_t ks_a[2] = { smem_u32(Ksb), smem_u32(Ksb + 64 * ALD) };
    const uint32_t vs_a[2] = { smem_u32(Vsb), smem_u32(Vsb + 64 * ALD) };

    // prefetch Q tile + K/V tile 0 (one group)
#pragma unroll
    for (int i = 0; i < 8; i++) {
        int c = t + i * 256;              // 2048 16B-chunks
        int row = c >> 4, ch = c & 15;
        cp16(qs_a + ((uint32_t)row * ALD + ch * 4) * 4,
             qptr + (size_t)(q0 + row) * HDIM + ch * 4);
    }
#pragma unroll
    for (int i = 0; i < 4; i++) {
        int c = t + i * 256;              // 1024 chunks each
        int row = c >> 4, ch = c & 15;
        uint32_t off = ((uint32_t)row * ALD + ch * 4) * 4;
        cp16(ks_a[0] + off, kptr + (size_t)row * HDIM + ch * 4);
        cp16(vs_a[0] + off, vptr + (size_t)row * HDIM + ch * 4);
    }
    cp_commit();

    float oacc[8][4];
#pragma unroll
    for (int nt = 0; nt < 8; nt++)
#pragma unroll
        for (int r = 0; r < 4; r++) oacc[nt][r] = 0.f;
    float m0 = -1e30f, m1 = -1e30f, l0 = 0.f, l1 = 0.f;

    const int wrow = w * 16;
    const int qg0 = q0 + wrow + qr;
    const int qg1 = qg0 + 8;
    const int qmax = q0 + wrow + 15;
    const int nj = blockIdx.x * 2 + 2;

    for (int jt = 0; jt < nj; jt++) {
        const int j0 = jt * 64;
        asm volatile("cp.async.wait_group 0;" ::: "memory");
        __syncthreads();

        if (jt + 1 < nj) {
            const int buf = (jt + 1) & 1;
            const int jr = (jt + 1) * 64;
#pragma unroll
            for (int i = 0; i < 4; i++) {
                int c = t + i * 256;
                int row = c >> 4, ch = c & 15;
                uint32_t off = ((uint32_t)row * ALD + ch * 4) * 4;
                cp16(ks_a[buf] + off, kptr + (size_t)(jr + row) * HDIM + ch * 4);
                cp16(vs_a[buf] + off, vptr + (size_t)(jr + row) * HDIM + ch * 4);
            }
            cp_commit();
        }
        if (j0 > qmax) continue;          // fully masked for this warp

        const float* Kf = Ksb + (jt & 1) * 64 * ALD;
        const float* Vf = Vsb + (jt & 1) * 64 * ALD;

        // ---- S = Q @ K^T ----
        float sacc[8][4];
#pragma unroll
        for (int nt = 0; nt < 8; nt++)
#pragma unroll
            for (int r = 0; r < 4; r++) sacc[nt][r] = 0.f;

#pragma unroll
        for (int ks = 0; ks < 8; ks++) {
            const int k = ks * 8;
            uint32_t a0 = cvt_tf32(Qs[(wrow + qr) * ALD + k + qc]);
            uint32_t a1 = cvt_tf32(Qs[(wrow + qr + 8) * ALD + k + qc]);
            uint32_t a2 = cvt_tf32(Qs[(wrow + qr) * ALD + k + qc + 4]);
            uint32_t a3 = cvt_tf32(Qs[(wrow + qr + 8) * ALD + k + qc + 4]);
#pragma unroll
            for (int nt = 0; nt < 8; nt++) {
                uint32_t b0 = cvt_tf32(Kf[(nt * 8 + qr) * ALD + k + qc]);
                uint32_t b1 = cvt_tf32(Kf[(nt * 8 + qr) * ALD + k + qc + 4]);
                mma_tf32(sacc[nt], a0, a1, a2, a3, b0, b1);
            }
        }

        // ---- causal mask + row max ----
        float rx0 = -1e30f, rx1 = -1e30f;
#pragma unroll
        for (int nt = 0; nt < 8; nt++) {
            int kg = j0 + nt * 8 + qc * 2;
            if (kg > qg0)     sacc[nt][0] = -1e30f;
            if (kg + 1 > qg0) sacc[nt][1] = -1e30f;
            if (kg > qg1)     sacc[nt][2] = -1e30f;
            if (kg + 1 > qg1) sacc[nt][3] = -1e30f;
            rx0 = fmaxf(rx0, fmaxf(sacc[nt][0], sacc[nt][1]));
            rx1 = fmaxf(rx1, fmaxf(sacc[nt][2], sacc[nt][3]));
        }
        rx0 = fmaxf(rx0, __shfl_xor_sync(0xffffffffu, rx0, 1));
        rx0 = fmaxf(rx0, __shfl_xor_sync(0xffffffffu, rx0, 2));
        rx1 = fmaxf(rx1, __shfl_xor_sync(0xffffffffu, rx1, 1));
        rx1 = fmaxf(rx1, __shfl_xor_sync(0xffffffffu, rx1, 2));

        float nm0 = fmaxf(m0, rx0), nm1 = fmaxf(m1, rx1);
        float cr0 = __expf(m0 - nm0), cr1 = __expf(m1 - nm1);

        // ---- exp, row sum, stage P (tf32) ----
        float rs0 = 0.f, rs1 = 0.f;
#pragma unroll
        for (int nt = 0; nt < 8; nt++) {
            float p00 = __expf(sacc[nt][0] - nm0);
            float p01 = __expf(sacc[nt][1] - nm0);
            float p10 = __expf(sacc[nt][2] - nm1);
            float p11 = __expf(sacc[nt][3] - nm1);
            rs0 += p00 + p01;
            rs1 += p10 + p11;
            uint32_t col = nt * 8 + qc * 2;
            *(uint2*)&Ps[(wrow + qr) * ALD + col]     = make_uint2(cvt_tf32(p00), cvt_tf32(p01));
            *(uint2*)&Ps[(wrow + qr + 8) * ALD + col] = make_uint2(cvt_tf32(p10), cvt_tf32(p11));
        }
        rs0 += __shfl_xor_sync(0xffffffffu, rs0, 1);
        rs0 += __shfl_xor_sync(0xffffffffu, rs0, 2);
        rs1 += __shfl_xor_sync(0xffffffffu, rs1, 1);
        rs1 += __shfl_xor_sync(0xffffffffu, rs1, 2);

        l0 = l0 * cr0 + rs0;  m0 = nm0;
        l1 = l1 * cr1 + rs1;  m1 = nm1;
#pragma unroll
        for (int nt = 0; nt < 8; nt++) {
            oacc[nt][0] *= cr0;  oacc[nt][1] *= cr0;
            oacc[nt][2] *= cr1;  oacc[nt][3] *= cr1;
        }
        __syncwarp();

        // ---- O += P @ V ----
#pragma unroll
        for (int ks = 0; ks < 8; ks++) {
            const int k = ks * 8;
            uint32_t a0 = Ps[(wrow + qr) * ALD + k + qc];
            uint32_t a1 = Ps[(wrow + qr + 8) * ALD + k + qc];
            uint32_t a2 = Ps[(wrow + qr) * ALD + k + qc + 4];
            uint32_t a3 = Ps[(wrow + qr + 8) * ALD + k + qc + 4];
#pragma unroll
            for (int nt = 0; nt < 8; nt++) {
                uint32_t b0 = cvt_tf32(Vf[(k + qc) * ALD + nt * 8 + qr]);
                uint32_t b1 = cvt_tf32(Vf[(k + qc + 4) * ALD + nt * 8 + qr]);
                mma_tf32(oacc[nt], a0, a1, a2, a3, b0, b1);
            }
        }
        __syncwarp();
    }

    // ---- epilogue: normalize, stage to smem, coalesced write ----
    __syncthreads();
    float* Pf = (float*)Ps;
    float inv0 = 1.f / l0, inv1 = 1.f / l1;
#pragma unroll
    for (int nt = 0; nt < 8; nt++) {
        uint32_t col = nt * 8 + qc * 2;
        *(float2*)&Pf[(wrow + qr) * ALD + col] =
            make_float2(oacc[nt][0] * inv0, oacc[nt][1] * inv0);
        *(float2*)&Pf[(wrow + qr + 8) * ALD + col] =
            make_float2(oacc[nt][2] * inv1, oacc[nt][3] * inv1);
    }
    __syncthreads();
    for (int idx = t; idx < 128 * 16; idx += 256) {
        int row = idx >> 4, ch = idx & 15;
        float4 v = *(float4*)&Pf[row * ALD + ch * 4];
        *(float4*)(g_a + ((size_t)b * SEQ + q0 + row) * NXD + h * HDIM + ch * 4) = v;
    }
}

// ---------------------------------------------------------------------------
extern "C" void kernel_launch(void* const* d_in, const int* in_sizes, int n_in,
                              void* d_out, int out_size)
{
    const float* x      = (const float*)d_in[0];
    const float* w_attn = (const float*)d_in[1];
    const float* b_attn = (const float*)d_in[2];
    const float* w_proj = (const float*)d_in[3];
    const float* b_proj = (const float*)d_in[4];

    float* out = (float*)d_out;
    float* present = out + (size_t)BATCH * SEQ * NXD;  // (2,B,NH,S,HD)

    cudaFuncSetAttribute(gemm_mma_kernel,
                         cudaFuncAttributeMaxDynamicSharedMemorySize, GEMM_SMEM);
    cudaFuncSetAttribute(attn_mma_kernel,
                         cudaFuncAttributeMaxDynamicSharedMemorySize, ATTN_SMEM);

    float* wT_attn;  cudaGetSymbolAddress((void**)&wT_attn, g_wT_attn);
    float* wT_proj;  cudaGetSymbolAddress((void**)&wT_proj, g_wT_proj);
    float* a_ptr;    cudaGetSymbolAddress((void**)&a_ptr, g_a);

    transpose_kernel<<<dim3(3 * NXD / 32, NXD / 32), 256>>>(w_attn, wT_attn, NXD, 3 * NXD);
    transpose_kernel<<<dim3(NXD / 32, NXD / 32), 256>>>(w_proj, wT_proj, NXD, NXD);

    gemm_mma_kernel<<<dim3(3 * NXD / 128, BATCH * SEQ / 128), 256, GEMM_SMEM>>>(
        x, wT_attn, b_attn, nullptr, present, 0);

    attn_mma_kernel<<<dim3(SEQ / 128, NHEAD, BATCH), 256, ATTN_SMEM>>>(present);

    gemm_mma_kernel<<<dim3(NXD / 128, BATCH * SEQ / 128), 256, GEMM_SMEM>>>(
        a_ptr, wT_proj, b_proj, out, nullptr, 1);
}

// round 6
// speedup vs baseline: 3.2475x; 1.1925x over previous
#include <cuda_runtime.h>
#include <cstdint>

#define BATCH 4
#define SEQ   1024
#define NXD   1024
#define NHEAD 16
#define HDIM  64
#define GK    1024

// Scratch (allocation-free rule: __device__ globals)
__device__ float g_q[(size_t)BATCH * NHEAD * SEQ * HDIM];   // tf32-rounded, pre-scaled
__device__ float g_a[(size_t)BATCH * SEQ * NXD];            // tf32-rounded
__device__ float g_x[(size_t)BATCH * SEQ * NXD];            // tf32-rounded copy of x
__device__ float g_wT_attn[(size_t)3 * NXD * NXD];          // tf32-rounded [3072,1024]
__device__ float g_wT_proj[(size_t)NXD * NXD];              // tf32-rounded [1024,1024]

__device__ __forceinline__ uint32_t smem_u32(const void* p) {
    uint32_t a;
    asm("{ .reg .u64 t; cvta.to.shared.u64 t, %1; cvt.u32.u64 %0, t; }"
        : "=r"(a) : "l"(p));
    return a;
}
__device__ __forceinline__ uint32_t cvt_tf32(float f) {
    uint32_t r;
    asm("cvt.rna.tf32.f32 %0, %1;" : "=r"(r) : "f"(f));
    return r;
}
__device__ __forceinline__ float rnd_tf32(float f) {
    return __uint_as_float(cvt_tf32(f));
}
__device__ __forceinline__ void cp16(uint32_t dst, const void* src) {
    asm volatile("cp.async.cg.shared.global [%0], [%1], 16;"
                 :: "r"(dst), "l"(src) : "memory");
}
__device__ __forceinline__ void cp_commit() {
    asm volatile("cp.async.commit_group;" ::: "memory");
}
__device__ __forceinline__ void mma_tf32(float* d,
    uint32_t a0, uint32_t a1, uint32_t a2, uint32_t a3,
    uint32_t b0, uint32_t b1)
{
    asm volatile(
        "mma.sync.aligned.m16n8k8.row.col.f32.tf32.tf32.f32 "
        "{%0,%1,%2,%3}, {%4,%5,%6,%7}, {%8,%9}, {%0,%1,%2,%3};"
        : "+f"(d[0]), "+f"(d[1]), "+f"(d[2]), "+f"(d[3])
        : "r"(a0), "r"(a1), "r"(a2), "r"(a3), "r"(b0), "r"(b1));
}

// ---------------------------------------------------------------------------
// elementwise tf32-round copy (x -> g_x)
// ---------------------------------------------------------------------------
__global__ void __launch_bounds__(256) cvt_copy_kernel(
    const float* __restrict__ src, float* __restrict__ dst)
{
    int i = blockIdx.x * 256 + threadIdx.x;
    float4 v = ((const float4*)src)[i];
    v.x = rnd_tf32(v.x); v.y = rnd_tf32(v.y);
    v.z = rnd_tf32(v.z); v.w = rnd_tf32(v.w);
    ((float4*)dst)[i] = v;
}

// ---------------------------------------------------------------------------
// weight transpose + tf32 round: dst[C][R] = rna(src[R][C])
// ---------------------------------------------------------------------------
__global__ void __launch_bounds__(256) transpose_kernel(
    const float* __restrict__ src, float* __restrict__ dst, int R, int C)
{
    __shared__ float tile[32][33];
    int c0 = blockIdx.x * 32, r0 = blockIdx.y * 32;
    int tx = threadIdx.x & 31, ty = threadIdx.x >> 5;
#pragma unroll
    for (int i = 0; i < 32; i += 8)
        tile[ty + i][tx] = src[(size_t)(r0 + ty + i) * C + c0 + tx];
    __syncthreads();
#pragma unroll
    for (int i = 0; i < 32; i += 8)
        dst[(size_t)(c0 + ty + i) * R + r0 + tx] = rnd_tf32(tile[tx][ty + i]);
}

// ---------------------------------------------------------------------------
// tf32 mma.sync GEMM, inputs pre-rounded to tf32 (NO cvt in mainloop).
// Block tile 128x256, BK=32, 8 warps (warp tile 64x64), 3-stage cp.async.
// C[m][n] = sum_k A[m][k] * BT[n][k] + bias[n]
// mode 0: scatter qkv (q scaled+rounded).  mode 1: store to Cout.
// ---------------------------------------------------------------------------
#define TLD 36
#define STG (384 * TLD)                 // floats per stage (A 128 + B 256 rows)
#define GEMM_SMEM (3 * STG * 4)         // 165,888 B

__global__ void __launch_bounds__(256) gemm_mma_kernel(
    const float* __restrict__ A, const float* __restrict__ BT,
    const float* __restrict__ bias, float* __restrict__ Cout,
    float* __restrict__ present, int mode)
{
    extern __shared__ float sm[];

    const int t = threadIdx.x;
    const int lane = t & 31, w = t >> 5;
    const int wm = w >> 2, wn = w & 3;          // 2 x 4 warp grid, 64x64 each
    const int qr = lane >> 2, qc = lane & 3;
    const int m0 = blockIdx.y * 128;
    const int n0 = blockIdx.x * 256;

    uint32_t sa_[3], sb_[3];
#pragma unroll
    for (int s = 0; s < 3; s++) {
        sa_[s] = smem_u32(sm + s * STG);
        sb_[s] = sa_[s] + 128 * TLD * 4;
    }

    float acc[4][8][4];
#pragma unroll
    for (int mt = 0; mt < 4; mt++)
#pragma unroll
        for (int nt = 0; nt < 8; nt++)
#pragma unroll
            for (int r = 0; r < 4; r++) acc[mt][nt][r] = 0.f;

    // A: 1024 16B-chunks (128 rows x 8), B: 2048 chunks (256 rows x 8)
#pragma unroll
    for (int s = 0; s < 2; s++) {
        const int k0 = s * 32;
#pragma unroll
        for (int i = 0; i < 4; i++) {
            int idx = t + i * 256;
            int row = idx >> 3, ch = idx & 7;
            cp16(sa_[s] + ((uint32_t)row * TLD + ch * 4) * 4,
                 A + (size_t)(m0 + row) * GK + k0 + ch * 4);
        }
#pragma unroll
        for (int i = 0; i < 8; i++) {
            int idx = t + i * 256;
            int row = idx >> 3, ch = idx & 7;
            cp16(sb_[s] + ((uint32_t)row * TLD + ch * 4) * 4,
                 BT + (size_t)(n0 + row) * GK + k0 + ch * 4);
        }
        cp_commit();
    }

    for (int kb = 0; kb < 32; kb++) {
        if (kb < 30)
            asm volatile("cp.async.wait_group 1;" ::: "memory");
        else
            asm volatile("cp.async.wait_group 0;" ::: "memory");
        __syncthreads();

        if (kb + 2 < 32) {
            const int s = (kb + 2) % 3;
            const int k0 = (kb + 2) * 32;
#pragma unroll
            for (int i = 0; i < 4; i++) {
                int idx = t + i * 256;
                int row = idx >> 3, ch = idx & 7;
                cp16(sa_[s] + ((uint32_t)row * TLD + ch * 4) * 4,
                     A + (size_t)(m0 + row) * GK + k0 + ch * 4);
            }
#pragma unroll
            for (int i = 0; i < 8; i++) {
                int idx = t + i * 256;
                int row = idx >> 3, ch = idx & 7;
                cp16(sb_[s] + ((uint32_t)row * TLD + ch * 4) * 4,
                     BT + (size_t)(n0 + row) * GK + k0 + ch * 4);
            }
            cp_commit();
        }

        const uint32_t* ab = (const uint32_t*)(sm + (kb % 3) * STG);
        const uint32_t* bb = ab + 128 * TLD;
#pragma unroll
        for (int ks = 0; ks < 4; ks++) {
            const int k = ks * 8;
            uint32_t af[4][4], bf[8][2];
#pragma unroll
            for (int mt = 0; mt < 4; mt++) {
                const uint32_t* ap = ab + (wm * 64 + mt * 16 + qr) * TLD + k + qc;
                af[mt][0] = ap[0];
                af[mt][1] = ap[8 * TLD];
                af[mt][2] = ap[4];
                af[mt][3] = ap[8 * TLD + 4];
            }
#pragma unroll
            for (int nt = 0; nt < 8; nt++) {
                const uint32_t* bp = bb + (wn * 64 + nt * 8 + qr) * TLD + k + qc;
                bf[nt][0] = bp[0];
                bf[nt][1] = bp[4];
            }
#pragma unroll
            for (int mt = 0; mt < 4; mt++)
#pragma unroll
                for (int nt = 0; nt < 8; nt++)
                    mma_tf32(acc[mt][nt], af[mt][0], af[mt][1], af[mt][2], af[mt][3],
                             bf[nt][0], bf[nt][1]);
        }
    }

#pragma unroll
    for (int mt = 0; mt < 4; mt++) {
#pragma unroll
        for (int nt = 0; nt < 8; nt++) {
            int row = m0 + wm * 64 + mt * 16 + qr;
            int col = n0 + wn * 64 + nt * 8 + qc * 2;
            float bv0 = bias[col], bv1 = bias[col + 1];
            float v00 = acc[mt][nt][0] + bv0, v01 = acc[mt][nt][1] + bv1;
            float v10 = acc[mt][nt][2] + bv0, v11 = acc[mt][nt][3] + bv1;
            if (mode == 1) {
                *(float2*)(Cout + (size_t)row * NXD + col) = make_float2(v00, v01);
                *(float2*)(Cout + (size_t)(row + 8) * NXD + col) = make_float2(v10, v11);
            } else {
                int sec = col >> 10;
                int hn = col & 1023;
                int h = hn >> 6, d = hn & 63;
                if (sec == 0) {   // q: fold softmax scale + tf32 pre-round
                    v00 = rnd_tf32(v00 * 0.125f); v01 = rnd_tf32(v01 * 0.125f);
                    v10 = rnd_tf32(v10 * 0.125f); v11 = rnd_tf32(v11 * 0.125f);
                }
                int b0_ = row >> 10, s0_ = row & 1023;
                size_t i0 = (((size_t)b0_ * NHEAD + h) * SEQ + s0_) * HDIM + d;
                int b1_ = (row + 8) >> 10, s1_ = (row + 8) & 1023;
                size_t i1 = (((size_t)b1_ * NHEAD + h) * SEQ + s1_) * HDIM + d;
                float* base = (sec == 0) ? g_q
                            : (sec == 1) ? present
                            : present + (size_t)BATCH * NHEAD * SEQ * HDIM;
                *(float2*)(base + i0) = make_float2(v00, v01);
                *(float2*)(base + i1) = make_float2(v10, v11);
            }
        }
    }
}

// ---------------------------------------------------------------------------
// Attention via tf32 mma.sync, FA2 fragment softmax, cp.async double-buffered.
// Q pre-rounded (raw frag loads); K/V exact fp32 (cvt at frag read);
// output g_a stored tf32-rounded for the proj GEMM.
// ---------------------------------------------------------------------------
#define ALD 68
#define ATTN_SMEM (512 * ALD * 4)   // 139,264 B

__global__ void __launch_bounds__(256, 1) attn_mma_kernel(const float* __restrict__ present)
{
    extern __shared__ float sma[];
    float* Qs = sma;                          // [128][ALD] tf32 bits
    float* Ksb = Qs + 128 * ALD;              // 2 x [64][ALD] (kpos, d)
    float* Vsb = Ksb + 2 * 64 * ALD;          // 2 x [64][ALD] (kpos, d)
    uint32_t* Ps = (uint32_t*)(Vsb + 2 * 64 * ALD);  // [128][ALD]

    const int t = threadIdx.x;
    const int lane = t & 31, w = t >> 5;
    const int qr = lane >> 2, qc = lane & 3;
    const int q0 = blockIdx.x * 128;
    const int h = blockIdx.y;
    const int b = blockIdx.z;

    const float* qptr = g_q + ((size_t)b * NHEAD + h) * SEQ * HDIM;
    const float* kptr = present + ((size_t)b * NHEAD + h) * SEQ * HDIM;
    const float* vptr = kptr + (size_t)BATCH * NHEAD * SEQ * HDIM;

    const uint32_t qs_a = smem_u32(Qs);
    const uint32_t ks_a[2] = { smem_u32(Ksb), smem_u32(Ksb + 64 * ALD) };
    const uint32_t vs_a[2] = { smem_u32(Vsb), smem_u32(Vsb + 64 * ALD) };

#pragma unroll
    for (int i = 0; i < 8; i++) {
        int c = t + i * 256;
        int row = c >> 4, ch = c & 15;
        cp16(qs_a + ((uint32_t)row * ALD + ch * 4) * 4,
             qptr + (size_t)(q0 + row) * HDIM + ch * 4);
    }
#pragma unroll
    for (int i = 0; i < 4; i++) {
        int c = t + i * 256;
        int row = c >> 4, ch = c & 15;
        uint32_t off = ((uint32_t)row * ALD + ch * 4) * 4;
        cp16(ks_a[0] + off, kptr + (size_t)row * HDIM + ch * 4);
        cp16(vs_a[0] + off, vptr + (size_t)row * HDIM + ch * 4);
    }
    cp_commit();

    float oacc[8][4];
#pragma unroll
    for (int nt = 0; nt < 8; nt++)
#pragma unroll
        for (int r = 0; r < 4; r++) oacc[nt][r] = 0.f;
    float m0 = -1e30f, m1 = -1e30f, l0 = 0.f, l1 = 0.f;

    const int wrow = w * 16;
    const int qg0 = q0 + wrow + qr;
    const int qg1 = qg0 + 8;
    const int qmax = q0 + wrow + 15;
    const int nj = blockIdx.x * 2 + 2;

    for (int jt = 0; jt < nj; jt++) {
        const int j0 = jt * 64;
        asm volatile("cp.async.wait_group 0;" ::: "memory");
        __syncthreads();

        if (jt + 1 < nj) {
            const int buf = (jt + 1) & 1;
            const int jr = (jt + 1) * 64;
#pragma unroll
            for (int i = 0; i < 4; i++) {
                int c = t + i * 256;
                int row = c >> 4, ch = c & 15;
                uint32_t off = ((uint32_t)row * ALD + ch * 4) * 4;
                cp16(ks_a[buf] + off, kptr + (size_t)(jr + row) * HDIM + ch * 4);
                cp16(vs_a[buf] + off, vptr + (size_t)(jr + row) * HDIM + ch * 4);
            }
            cp_commit();
        }
        if (j0 > qmax) continue;

        const float* Kf = Ksb + (jt & 1) * 64 * ALD;
        const float* Vf = Vsb + (jt & 1) * 64 * ALD;
        const uint32_t* Qu = (const uint32_t*)Qs;

        // ---- S = Q @ K^T ----
        float sacc[8][4];
#pragma unroll
        for (int nt = 0; nt < 8; nt++)
#pragma unroll
            for (int r = 0; r < 4; r++) sacc[nt][r] = 0.f;

#pragma unroll
        for (int ks = 0; ks < 8; ks++) {
            const int k = ks * 8;
            uint32_t a0 = Qu[(wrow + qr) * ALD + k + qc];
            uint32_t a1 = Qu[(wrow + qr + 8) * ALD + k + qc];
            uint32_t a2 = Qu[(wrow + qr) * ALD + k + qc + 4];
            uint32_t a3 = Qu[(wrow + qr + 8) * ALD + k + qc + 4];
#pragma unroll
            for (int nt = 0; nt < 8; nt++) {
                uint32_t b0 = cvt_tf32(Kf[(nt * 8 + qr) * ALD + k + qc]);
                uint32_t b1 = cvt_tf32(Kf[(nt * 8 + qr) * ALD + k + qc + 4]);
                mma_tf32(sacc[nt], a0, a1, a2, a3, b0, b1);
            }
        }

        // ---- causal mask + row max ----
        float rx0 = -1e30f, rx1 = -1e30f;
#pragma unroll
        for (int nt = 0; nt < 8; nt++) {
            int kg = j0 + nt * 8 + qc * 2;
            if (kg > qg0)     sacc[nt][0] = -1e30f;
            if (kg + 1 > qg0) sacc[nt][1] = -1e30f;
            if (kg > qg1)     sacc[nt][2] = -1e30f;
            if (kg + 1 > qg1) sacc[nt][3] = -1e30f;
            rx0 = fmaxf(rx0, fmaxf(sacc[nt][0], sacc[nt][1]));
            rx1 = fmaxf(rx1, fmaxf(sacc[nt][2], sacc[nt][3]));
        }
        rx0 = fmaxf(rx0, __shfl_xor_sync(0xffffffffu, rx0, 1));
        rx0 = fmaxf(rx0, __shfl_xor_sync(0xffffffffu, rx0, 2));
        rx1 = fmaxf(rx1, __shfl_xor_sync(0xffffffffu, rx1, 1));
        rx1 = fmaxf(rx1, __shfl_xor_sync(0xffffffffu, rx1, 2));

        float nm0 = fmaxf(m0, rx0), nm1 = fmaxf(m1, rx1);
        float cr0 = __expf(m0 - nm0), cr1 = __expf(m1 - nm1);

        // ---- exp, row sum, stage P (tf32) ----
        float rs0 = 0.f, rs1 = 0.f;
#pragma unroll
        for (int nt = 0; nt < 8; nt++) {
            float p00 = __expf(sacc[nt][0] - nm0);
            float p01 = __expf(sacc[nt][1] - nm0);
            float p10 = __expf(sacc[nt][2] - nm1);
            float p11 = __expf(sacc[nt][3] - nm1);
            rs0 += p00 + p01;
            rs1 += p10 + p11;
            uint32_t col = nt * 8 + qc * 2;
            *(uint2*)&Ps[(wrow + qr) * ALD + col]     = make_uint2(cvt_tf32(p00), cvt_tf32(p01));
            *(uint2*)&Ps[(wrow + qr + 8) * ALD + col] = make_uint2(cvt_tf32(p10), cvt_tf32(p11));
        }
        rs0 += __shfl_xor_sync(0xffffffffu, rs0, 1);
        rs0 += __shfl_xor_sync(0xffffffffu, rs0, 2);
        rs1 += __shfl_xor_sync(0xffffffffu, rs1, 1);
        rs1 += __shfl_xor_sync(0xffffffffu, rs1, 2);

        l0 = l0 * cr0 + rs0;  m0 = nm0;
        l1 = l1 * cr1 + rs1;  m1 = nm1;
#pragma unroll
        for (int nt = 0; nt < 8; nt++) {
            oacc[nt][0] *= cr0;  oacc[nt][1] *= cr0;
            oacc[nt][2] *= cr1;  oacc[nt][3] *= cr1;
        }
        __syncwarp();

        // ---- O += P @ V ----
#pragma unroll
        for (int ks = 0; ks < 8; ks++) {
            const int k = ks * 8;
            uint32_t a0 = Ps[(wrow + qr) * ALD + k + qc];
            uint32_t a1 = Ps[(wrow + qr + 8) * ALD + k + qc];
            uint32_t a2 = Ps[(wrow + qr) * ALD + k + qc + 4];
            uint32_t a3 = Ps[(wrow + qr + 8) * ALD + k + qc + 4];
#pragma unroll
            for (int nt = 0; nt < 8; nt++) {
                uint32_t b0 = cvt_tf32(Vf[(k + qc) * ALD + nt * 8 + qr]);
                uint32_t b1 = cvt_tf32(Vf[(k + qc + 4) * ALD + nt * 8 + qr]);
                mma_tf32(oacc[nt], a0, a1, a2, a3, b0, b1);
            }
        }
        __syncwarp();
    }

    // ---- epilogue: normalize, stage, tf32-round, coalesced write ----
    __syncthreads();
    float* Pf = (float*)Ps;
    float inv0 = 1.f / l0, inv1 = 1.f / l1;
#pragma unroll
    for (int nt = 0; nt < 8; nt++) {
        uint32_t col = nt * 8 + qc * 2;
        *(float2*)&Pf[(wrow + qr) * ALD + col] =
            make_float2(oacc[nt][0] * inv0, oacc[nt][1] * inv0);
        *(float2*)&Pf[(wrow + qr + 8) * ALD + col] =
            make_float2(oacc[nt][2] * inv1, oacc[nt][3] * inv1);
    }
    __syncthreads();
    for (int idx = t; idx < 128 * 16; idx += 256) {
        int row = idx >> 4, ch = idx & 15;
        float4 v = *(float4*)&Pf[row * ALD + ch * 4];
        v.x = rnd_tf32(v.x); v.y = rnd_tf32(v.y);
        v.z = rnd_tf32(v.z); v.w = rnd_tf32(v.w);
        *(float4*)(g_a + ((size_t)b * SEQ + q0 + row) * NXD + h * HDIM + ch * 4) = v;
    }
}

// ---------------------------------------------------------------------------
extern "C" void kernel_launch(void* const* d_in, const int* in_sizes, int n_in,
                              void* d_out, int out_size)
{
    const float* x      = (const float*)d_in[0];
    const float* w_attn = (const float*)d_in[1];
    const float* b_attn = (const float*)d_in[2];
    const float* w_proj = (const float*)d_in[3];
    const float* b_proj = (const float*)d_in[4];

    float* out = (float*)d_out;
    float* present = out + (size_t)BATCH * SEQ * NXD;  // (2,B,NH,S,HD)

    cudaFuncSetAttribute(gemm_mma_kernel,
                         cudaFuncAttributeMaxDynamicSharedMemorySize, GEMM_SMEM);
    cudaFuncSetAttribute(attn_mma_kernel,
                         cudaFuncAttributeMaxDynamicSharedMemorySize, ATTN_SMEM);

    float* wT_attn;  cudaGetSymbolAddress((void**)&wT_attn, g_wT_attn);
    float* wT_proj;  cudaGetSymbolAddress((void**)&wT_proj, g_wT_proj);
    float* a_ptr;    cudaGetSymbolAddress((void**)&a_ptr, g_a);
    float* x_ptr;    cudaGetSymbolAddress((void**)&x_ptr, g_x);

    cvt_copy_kernel<<<(BATCH * SEQ * NXD / 4) / 256, 256>>>(x, x_ptr);
    transpose_kernel<<<dim3(3 * NXD / 32, NXD / 32), 256>>>(w_attn, wT_attn, NXD, 3 * NXD);
    transpose_kernel<<<dim3(NXD / 32, NXD / 32), 256>>>(w_proj, wT_proj, NXD, NXD);

    gemm_mma_kernel<<<dim3(3 * NXD / 256, BATCH * SEQ / 128), 256, GEMM_SMEM>>>(
        x_ptr, wT_attn, b_attn, nullptr, present, 0);

    attn_mma_kernel<<<dim3(SEQ / 128, NHEAD, BATCH), 256, ATTN_SMEM>>>(present);

    gemm_mma_kernel<<<dim3(NXD / 256, BATCH * SEQ / 128), 256, GEMM_SMEM>>>(
        a_ptr, wT_proj, b_proj, out, nullptr, 1);
}